// round 1
// baseline (speedup 1.0000x reference)
#include <cuda_runtime.h>
#include <math.h>

// Problem constants
#define BATCH 256
#define NSTEP 32           // T*D = 8*4
#define NIMG  (BATCH*NSTEP) // 8192

// Output layout (float32):
//   [0, 81920)            all_cnn_preds   (32,256,10)
//   [81920, 131072)       all_guard_preds (32,256,6)
//   [131072, 133632)      state_final     (256,10)
#define GUARD_BASE 81920
#define STATE_BASE 131072

// ---------------------------------------------------------------------------
// Fused CNN: conv1->relu->pool -> conv2->relu->pool -> conv3->relu->pool
//            -> dense -> softmax -> digit_to_rule
// One CTA per image; all intermediates in shared memory.
// ---------------------------------------------------------------------------
__global__ __launch_bounds__(256, 4) void cnn_kernel(
    const float* __restrict__ seq,
    const float* __restrict__ c1w, const float* __restrict__ c1b,
    const float* __restrict__ c2w, const float* __restrict__ c2b,
    const float* __restrict__ c3w, const float* __restrict__ c3b,
    const float* __restrict__ dw,  const float* __restrict__ db,
    float* __restrict__ out)
{
    __shared__ float s_img[784];        // 28x28 input
    __shared__ float s1[8 * 13 * 13];   // pooled conv1 (1352)
    __shared__ float s2[16 * 5 * 5];    // pooled conv2 (400)
    __shared__ float s3t[128];          // conv3 relu per (oc, pos)
    __shared__ float s3[32];            // pooled conv3
    __shared__ float s_w1[72],  s_b1[8];
    __shared__ float s_w2[1152], s_b2[16];
    __shared__ float s_w3[4608], s_b3[32];
    __shared__ float s_dw[320], s_db[10];
    __shared__ float s_logits[10];
    __shared__ float s_p[10];

    const int tid = threadIdx.x;
    const int img = blockIdx.x;
    const int n = img >> 8;      // step index 0..31
    const int b = img & 255;     // batch index
    // sequences layout (B, T*D, 28, 28); image order is (n, b)
    const float* ip = seq + ((long)b * NSTEP + n) * 784;

    for (int k = tid; k < 784; k += 256)  s_img[k] = ip[k];
    for (int k = tid; k < 72;  k += 256)  s_w1[k] = c1w[k];
    if (tid < 8)  s_b1[tid] = c1b[tid];
    for (int k = tid; k < 1152; k += 256) s_w2[k] = c2w[k];
    if (tid < 16) s_b2[tid] = c2b[tid];
    for (int k = tid; k < 4608; k += 256) s_w3[k] = c3w[k];
    if (tid < 32) s_b3[tid] = c3b[tid];
    for (int k = tid; k < 320; k += 256)  s_dw[k] = dw[k];
    if (tid < 10) s_db[tid] = db[tid];
    __syncthreads();

    // ---- Stage 1: conv1(1->8, 3x3) + relu + avgpool2 -> 8x13x13 ----
    for (int idx = tid; idx < 1352; idx += 256) {
        const int c   = idx / 169;
        const int rem = idx - c * 169;
        const int y   = rem / 13;
        const int x   = rem - y * 13;
        const int iy = 2 * y, ix = 2 * x;

        float win[4][4];
        #pragma unroll
        for (int r = 0; r < 4; r++)
            #pragma unroll
            for (int cc = 0; cc < 4; cc++)
                win[r][cc] = s_img[(iy + r) * 28 + ix + cc];

        float w[9];
        #pragma unroll
        for (int k = 0; k < 9; k++) w[k] = s_w1[c * 9 + k];
        const float bias = s_b1[c];

        float acc = 0.f;
        #pragma unroll
        for (int dy = 0; dy < 2; dy++)
            #pragma unroll
            for (int dx = 0; dx < 2; dx++) {
                float v = bias;
                #pragma unroll
                for (int ky = 0; ky < 3; ky++)
                    #pragma unroll
                    for (int kx = 0; kx < 3; kx++)
                        v += win[dy + ky][dx + kx] * w[ky * 3 + kx];
                acc += fmaxf(v, 0.f);
            }
        s1[idx] = acc * 0.25f;
    }
    __syncthreads();

    // ---- Stage 2: conv2(8->16, 3x3) + relu + avgpool2 -> 16x5x5 ----
    for (int idx = tid; idx < 400; idx += 256) {
        const int oc  = idx / 25;
        const int rem = idx - oc * 25;
        const int y   = rem / 5;
        const int x   = rem - y * 5;
        const int iy = 2 * y, ix = 2 * x;

        const float bias = s_b2[oc];
        float v00 = bias, v01 = bias, v10 = bias, v11 = bias;
        #pragma unroll
        for (int ic = 0; ic < 8; ic++) {
            const float* sp = &s1[ic * 169 + iy * 13 + ix];
            float win[4][4];
            #pragma unroll
            for (int r = 0; r < 4; r++)
                #pragma unroll
                for (int cc = 0; cc < 4; cc++)
                    win[r][cc] = sp[r * 13 + cc];
            const float* wp = &s_w2[(oc * 8 + ic) * 9];
            #pragma unroll
            for (int ky = 0; ky < 3; ky++)
                #pragma unroll
                for (int kx = 0; kx < 3; kx++) {
                    const float w = wp[ky * 3 + kx];
                    v00 += win[ky    ][kx    ] * w;
                    v01 += win[ky    ][kx + 1] * w;
                    v10 += win[ky + 1][kx    ] * w;
                    v11 += win[ky + 1][kx + 1] * w;
                }
        }
        s2[idx] = 0.25f * (fmaxf(v00, 0.f) + fmaxf(v01, 0.f) +
                           fmaxf(v10, 0.f) + fmaxf(v11, 0.f));
    }
    __syncthreads();

    // ---- Stage 3: conv3(16->32, 3x3) + relu, 2x2 of the 3x3 outputs ----
    if (tid < 128) {
        const int oc  = tid >> 2;
        const int pos = tid & 3;
        const int dy = pos >> 1, dx = pos & 1;
        float v = s_b3[oc];
        #pragma unroll
        for (int ic = 0; ic < 16; ic++) {
            const float* sp = &s2[ic * 25 + dy * 5 + dx];
            const float* wp = &s_w3[(oc * 16 + ic) * 9];
            #pragma unroll
            for (int ky = 0; ky < 3; ky++)
                #pragma unroll
                for (int kx = 0; kx < 3; kx++)
                    v += sp[ky * 5 + kx] * wp[ky * 3 + kx];
        }
        s3t[tid] = fmaxf(v, 0.f);
    }
    __syncthreads();
    if (tid < 32)
        s3[tid] = 0.25f * (s3t[tid * 4] + s3t[tid * 4 + 1] +
                           s3t[tid * 4 + 2] + s3t[tid * 4 + 3]);
    __syncthreads();

    // ---- Dense(32->10) + softmax ----
    if (tid < 10) {
        float v = s_db[tid];
        #pragma unroll
        for (int j = 0; j < 32; j++) v += s3[j] * s_dw[tid * 32 + j];
        s_logits[tid] = v;
    }
    __syncthreads();
    if (tid < 10) {
        float m = s_logits[0];
        #pragma unroll
        for (int j = 1; j < 10; j++) m = fmaxf(m, s_logits[j]);
        float sum = 0.f;
        #pragma unroll
        for (int j = 0; j < 10; j++) sum += expf(s_logits[j] - m);
        const float p = expf(s_logits[tid] - m) / sum;
        s_p[tid] = p;
        out[img * 10 + tid] = p;               // all_cnn_preds[n][b][tid]
    }
    __syncthreads();

    // ---- digit_to_rule -> guard probs ----
    if (tid < 6) {
        float g;
        switch (tid) {
            case 0:  g = s_p[8];            break;
            case 1:  g = s_p[4] + s_p[6];   break;
            case 2:  g = s_p[0] + s_p[2];   break;
            case 3:  g = s_p[7] + s_p[9];   break;
            case 4:  g = s_p[5];            break;
            default: g = s_p[1] + s_p[3];   break;
        }
        out[GUARD_BASE + img * 6 + tid] = g;   // all_guard_preds[n][b][tid]
    }
}

// ---------------------------------------------------------------------------
// SFA recurrence: one warp per batch element b.
// Each block rebuilds M = softmax(trans/0.1) (+ accepting row) in smem,
// then runs 32 sequential steps: state <- state @ (sum_r g_r M_r).
// ---------------------------------------------------------------------------
__global__ __launch_bounds__(32) void sfa_kernel(
    const float* __restrict__ trans,
    float* __restrict__ out)
{
    __shared__ float M[600];      // (6,10,10)
    __shared__ float state[10];

    const int tid = threadIdx.x;  // 0..31
    const int b   = blockIdx.x;   // 0..255

    // softmax(trans*10) for rows 0..8 of each of 6 rules (54 rows)
    for (int row = tid; row < 54; row += 32) {
        const int r = row / 9, i = row - r * 9;
        const float* tp = trans + (r * 9 + i) * 10;
        float m = tp[0] * 10.f;
        #pragma unroll
        for (int j = 1; j < 10; j++) m = fmaxf(m, tp[j] * 10.f);
        float e[10];
        float s = 0.f;
        #pragma unroll
        for (int j = 0; j < 10; j++) { e[j] = expf(tp[j] * 10.f - m); s += e[j]; }
        const float inv = 1.f / s;
        #pragma unroll
        for (int j = 0; j < 10; j++) M[r * 100 + i * 10 + j] = e[j] * inv;
    }
    // accepting row: M[r][9][:] = e_9
    if (tid < 6) {
        #pragma unroll
        for (int j = 0; j < 10; j++) M[tid * 100 + 90 + j] = (j == 9) ? 1.f : 0.f;
    }
    if (tid < 10) state[tid] = (tid == 0) ? 1.f : 0.f;
    __syncthreads();

    const float* gbase = out + GUARD_BASE;
    for (int n = 0; n < NSTEP; n++) {
        const float* gp = gbase + (n * BATCH + b) * 6;
        const float g0 = gp[0], g1 = gp[1], g2 = gp[2],
                    g3 = gp[3], g4 = gp[4], g5 = gp[5];
        float acc = 0.f;
        if (tid < 10) {
            #pragma unroll
            for (int i = 0; i < 10; i++) {
                const float a =
                    g0 * M[        i * 10 + tid] +
                    g1 * M[100 +   i * 10 + tid] +
                    g2 * M[200 +   i * 10 + tid] +
                    g3 * M[300 +   i * 10 + tid] +
                    g4 * M[400 +   i * 10 + tid] +
                    g5 * M[500 +   i * 10 + tid];
                acc += state[i] * a;
            }
        }
        __syncthreads();
        if (tid < 10) state[tid] = acc;
        __syncthreads();
    }
    if (tid < 10) out[STATE_BASE + b * 10 + tid] = state[tid];
}

// ---------------------------------------------------------------------------
extern "C" void kernel_launch(void* const* d_in, const int* in_sizes, int n_in,
                              void* d_out, int out_size)
{
    const float* seq   = (const float*)d_in[0];
    const float* c1w   = (const float*)d_in[1];
    const float* c1b   = (const float*)d_in[2];
    const float* c2w   = (const float*)d_in[3];
    const float* c2b   = (const float*)d_in[4];
    const float* c3w   = (const float*)d_in[5];
    const float* c3b   = (const float*)d_in[6];
    const float* dw    = (const float*)d_in[7];
    const float* db    = (const float*)d_in[8];
    const float* trans = (const float*)d_in[9];
    float* out = (float*)d_out;

    cnn_kernel<<<NIMG, 256>>>(seq, c1w, c1b, c2w, c2b, c3w, c3b, dw, db, out);
    sfa_kernel<<<BATCH, 32>>>(trans, out);
}

// round 2
// speedup vs baseline: 1.0753x; 1.0753x over previous
#include <cuda_runtime.h>
#include <math.h>

#define BATCH 256
#define NSTEP 32
#define NIMG  (BATCH*NSTEP)

// Output layout (float32):
//   [0, 81920)        all_cnn_preds   (32,256,10)
//   [81920, 131072)   all_guard_preds (32,256,6)
//   [131072, 133632)  state_final     (256,10)
#define GUARD_BASE 81920
#define STATE_BASE 131072

// ---------------------------------------------------------------------------
// Fused CNN, one CTA per image. All intermediates in smem.
// Register-blocked (2 output channels / thread) + vectorized LDS.
// ---------------------------------------------------------------------------
__global__ __launch_bounds__(256) void cnn_kernel(
    const float* __restrict__ seq,
    const float* __restrict__ c1w, const float* __restrict__ c1b,
    const float* __restrict__ c2w, const float* __restrict__ c2b,
    const float* __restrict__ c3w, const float* __restrict__ c3b,
    const float* __restrict__ dw,  const float* __restrict__ db,
    float* __restrict__ out)
{
    __shared__ __align__(16) float s_img[784];          // 28x28
    __shared__ __align__(16) float s1p[8 * 13 * 14];    // pooled conv1, rows padded to 14
    __shared__ __align__(16) float s2[16 * 5 * 5];      // pooled conv2
    __shared__ float s3t[128];
    __shared__ float s3[32];
    __shared__ __align__(16) float s_w1p[8 * 12];       // conv1 w, padded to 12/ch
    __shared__ float s_b1[8];
    __shared__ __align__(16) float s_w2p[16 * 8 * 12];  // conv2 w, padded
    __shared__ float s_b2[16];
    __shared__ __align__(16) float s_w3p[32 * 16 * 12]; // conv3 w, padded
    __shared__ float s_b3[32];
    __shared__ float s_dw[320], s_db[10];
    __shared__ float s_logits[10];
    __shared__ float s_p[10];

    const int tid = threadIdx.x;
    const int img = blockIdx.x;
    const int n = img >> 8;
    const int b = img & 255;
    const float* ip = seq + ((long)b * NSTEP + n) * 784;

    for (int k = tid; k < 784; k += 256) s_img[k] = ip[k];
    if (tid < 8) {
        s_b1[tid] = c1b[tid];
        #pragma unroll
        for (int t = 0; t < 9; t++) s_w1p[tid * 12 + t] = c1w[tid * 9 + t];
    }
    if (tid < 128) {                      // 16*8 (oc,ic) pairs
        #pragma unroll
        for (int t = 0; t < 9; t++) s_w2p[tid * 12 + t] = c2w[tid * 9 + t];
    }
    if (tid < 16) s_b2[tid] = c2b[tid];
    for (int k = tid; k < 512; k += 256) { // 32*16 (oc,ic) pairs
        #pragma unroll
        for (int t = 0; t < 9; t++) s_w3p[k * 12 + t] = c3w[k * 9 + t];
    }
    if (tid < 32) s_b3[tid] = c3b[tid];
    for (int k = tid; k < 320; k += 256) s_dw[k] = dw[k];
    if (tid < 10) s_db[tid] = db[tid];
    __syncthreads();

    // ---- Stage 1: conv1(1->8) + relu + pool -> s1p (8,13,14-pad) ----
    // 4 channel-pairs x 169 positions = 676 items
    for (int idx = tid; idx < 676; idx += 256) {
        const int cp  = idx / 169;
        const int rem = idx - cp * 169;
        const int y   = rem / 13;
        const int x   = rem - y * 13;
        const int iy = 2 * y, ix = 2 * x;

        float win[4][4];
        #pragma unroll
        for (int r = 0; r < 4; r++) {
            const float2 a = *(const float2*)&s_img[(iy + r) * 28 + ix];
            const float2 c = *(const float2*)&s_img[(iy + r) * 28 + ix + 2];
            win[r][0] = a.x; win[r][1] = a.y; win[r][2] = c.x; win[r][3] = c.y;
        }

        #pragma unroll
        for (int h = 0; h < 2; h++) {
            const int c = 2 * cp + h;
            const float4 w0 = *(const float4*)&s_w1p[c * 12];
            const float4 w1 = *(const float4*)&s_w1p[c * 12 + 4];
            const float w8  = s_w1p[c * 12 + 8];
            const float w[9] = {w0.x, w0.y, w0.z, w0.w, w1.x, w1.y, w1.z, w1.w, w8};
            const float bias = s_b1[c];
            float acc = 0.f;
            #pragma unroll
            for (int dy = 0; dy < 2; dy++)
                #pragma unroll
                for (int dx = 0; dx < 2; dx++) {
                    float v = bias;
                    #pragma unroll
                    for (int ky = 0; ky < 3; ky++)
                        #pragma unroll
                        for (int kx = 0; kx < 3; kx++)
                            v += win[dy + ky][dx + kx] * w[ky * 3 + kx];
                    acc += fmaxf(v, 0.f);
                }
            s1p[c * 182 + y * 14 + x] = acc * 0.25f;
        }
    }
    __syncthreads();

    // ---- Stage 2: conv2(8->16) + relu + pool -> s2 (16,5,5) ----
    // 8 oc-pairs x 25 positions = 200 items, single pass
    if (tid < 200) {
        const int op  = tid / 25;
        const int rem = tid - op * 25;
        const int y   = rem / 5;
        const int x   = rem - y * 5;
        const int iy = 2 * y, ix = 2 * x;
        const int oc0 = 2 * op, oc1 = 2 * op + 1;

        const float b0 = s_b2[oc0], b1 = s_b2[oc1];
        float a00 = b0, a01 = b0, a10 = b0, a11 = b0;
        float c00 = b1, c01 = b1, c10 = b1, c11 = b1;

        #pragma unroll
        for (int ic = 0; ic < 8; ic++) {
            float win[4][4];
            #pragma unroll
            for (int r = 0; r < 4; r++) {
                const float2 u = *(const float2*)&s1p[ic * 182 + (iy + r) * 14 + ix];
                const float2 v = *(const float2*)&s1p[ic * 182 + (iy + r) * 14 + ix + 2];
                win[r][0] = u.x; win[r][1] = u.y; win[r][2] = v.x; win[r][3] = v.y;
            }
            const float4 u0 = *(const float4*)&s_w2p[(oc0 * 8 + ic) * 12];
            const float4 u1 = *(const float4*)&s_w2p[(oc0 * 8 + ic) * 12 + 4];
            const float u8  = s_w2p[(oc0 * 8 + ic) * 12 + 8];
            const float wa[9] = {u0.x, u0.y, u0.z, u0.w, u1.x, u1.y, u1.z, u1.w, u8};
            const float4 v0 = *(const float4*)&s_w2p[(oc1 * 8 + ic) * 12];
            const float4 v1 = *(const float4*)&s_w2p[(oc1 * 8 + ic) * 12 + 4];
            const float v8  = s_w2p[(oc1 * 8 + ic) * 12 + 8];
            const float wb[9] = {v0.x, v0.y, v0.z, v0.w, v1.x, v1.y, v1.z, v1.w, v8};

            #pragma unroll
            for (int ky = 0; ky < 3; ky++)
                #pragma unroll
                for (int kx = 0; kx < 3; kx++) {
                    const float wA = wa[ky * 3 + kx];
                    const float wB = wb[ky * 3 + kx];
                    const float p00 = win[ky    ][kx    ];
                    const float p01 = win[ky    ][kx + 1];
                    const float p10 = win[ky + 1][kx    ];
                    const float p11 = win[ky + 1][kx + 1];
                    a00 += p00 * wA; a01 += p01 * wA; a10 += p10 * wA; a11 += p11 * wA;
                    c00 += p00 * wB; c01 += p01 * wB; c10 += p10 * wB; c11 += p11 * wB;
                }
        }
        s2[oc0 * 25 + rem] = 0.25f * (fmaxf(a00, 0.f) + fmaxf(a01, 0.f) +
                                      fmaxf(a10, 0.f) + fmaxf(a11, 0.f));
        s2[oc1 * 25 + rem] = 0.25f * (fmaxf(c00, 0.f) + fmaxf(c01, 0.f) +
                                      fmaxf(c10, 0.f) + fmaxf(c11, 0.f));
    }
    __syncthreads();

    // ---- Stage 3: conv3(16->32) + relu, 2x2 positions ----
    if (tid < 128) {
        const int oc  = tid >> 2;
        const int pos = tid & 3;
        const int dy = pos >> 1, dx = pos & 1;
        float v = s_b3[oc];
        #pragma unroll
        for (int ic = 0; ic < 16; ic++) {
            const float* sp = &s2[ic * 25 + dy * 5 + dx];
            const float4 w0 = *(const float4*)&s_w3p[(oc * 16 + ic) * 12];
            const float4 w1 = *(const float4*)&s_w3p[(oc * 16 + ic) * 12 + 4];
            const float w8  = s_w3p[(oc * 16 + ic) * 12 + 8];
            v += sp[0]  * w0.x + sp[1]  * w0.y + sp[2]  * w0.z
               + sp[5]  * w0.w + sp[6]  * w1.x + sp[7]  * w1.y
               + sp[10] * w1.z + sp[11] * w1.w + sp[12] * w8;
        }
        s3t[tid] = fmaxf(v, 0.f);
    }
    __syncthreads();
    if (tid < 32)
        s3[tid] = 0.25f * (s3t[tid * 4] + s3t[tid * 4 + 1] +
                           s3t[tid * 4 + 2] + s3t[tid * 4 + 3]);
    __syncthreads();

    // ---- Dense(32->10) + softmax + digit_to_rule ----
    if (tid < 10) {
        float v = s_db[tid];
        #pragma unroll
        for (int j = 0; j < 32; j++) v += s3[j] * s_dw[tid * 32 + j];
        s_logits[tid] = v;
    }
    __syncthreads();
    if (tid < 10) {
        float m = s_logits[0];
        #pragma unroll
        for (int j = 1; j < 10; j++) m = fmaxf(m, s_logits[j]);
        float sum = 0.f;
        #pragma unroll
        for (int j = 0; j < 10; j++) sum += __expf(s_logits[j] - m);
        const float p = __expf(s_logits[tid] - m) / sum;
        s_p[tid] = p;
        out[img * 10 + tid] = p;
    }
    __syncthreads();
    if (tid < 6) {
        float g;
        switch (tid) {
            case 0:  g = s_p[8];          break;
            case 1:  g = s_p[4] + s_p[6]; break;
            case 2:  g = s_p[0] + s_p[2]; break;
            case 3:  g = s_p[7] + s_p[9]; break;
            case 4:  g = s_p[5];          break;
            default: g = s_p[1] + s_p[3]; break;
        }
        out[GUARD_BASE + img * 6 + tid] = g;
    }
}

// ---------------------------------------------------------------------------
// SFA recurrence: one warp per batch element. Guards prefetched to smem,
// state in registers, broadcast via shfl. No barriers in the main loop.
// ---------------------------------------------------------------------------
__global__ __launch_bounds__(32) void sfa_kernel(
    const float* __restrict__ trans,
    float* __restrict__ out)
{
    __shared__ float M[640];           // (6,10,10), padded
    __shared__ float s_g[NSTEP * 6];   // 192 guard values for this b

    const int tid = threadIdx.x;
    const int b   = blockIdx.x;

    // Prefetch all guards for this batch element
    const float* gbase = out + GUARD_BASE;
    for (int k = tid; k < NSTEP * 6; k += 32) {
        const int n = k / 6, j = k - n * 6;
        s_g[k] = gbase[(n * BATCH + b) * 6 + j];
    }

    // M = softmax(trans*10), rows 0..8 of 6 rules
    for (int row = tid; row < 54; row += 32) {
        const int r = row / 9, i = row - r * 9;
        const float* tp = trans + (r * 9 + i) * 10;
        float m = tp[0] * 10.f;
        #pragma unroll
        for (int j = 1; j < 10; j++) m = fmaxf(m, tp[j] * 10.f);
        float e[10];
        float s = 0.f;
        #pragma unroll
        for (int j = 0; j < 10; j++) { e[j] = __expf(tp[j] * 10.f - m); s += e[j]; }
        const float inv = 1.f / s;
        #pragma unroll
        for (int j = 0; j < 10; j++) M[r * 100 + i * 10 + j] = e[j] * inv;
    }
    if (tid < 6) {
        #pragma unroll
        for (int j = 0; j < 10; j++) M[tid * 100 + 90 + j] = (j == 9) ? 1.f : 0.f;
    }
    if (tid >= 26) {   // zero the padding so lanes >=10 stay finite
        M[600 + tid - 26] = 0.f;
        M[606 + tid - 26] = 0.f;
        M[612 + tid - 26] = 0.f;
        M[618 + tid - 26] = 0.f;
        M[624 + tid - 26] = 0.f;
        M[630 + tid - 26] = 0.f;
        if (tid - 26 < 4) M[636 + tid - 26] = 0.f;
    }
    __syncthreads();

    // Lane j (j<10) holds state[j]; all 32 lanes run the loop for shfl validity.
    float st = (tid == 0) ? 1.f : 0.f;
    const int jj = (tid < 10) ? tid : 0;

    for (int n = 0; n < NSTEP; n++) {
        const float g0 = s_g[n * 6 + 0], g1 = s_g[n * 6 + 1], g2 = s_g[n * 6 + 2];
        const float g3 = s_g[n * 6 + 3], g4 = s_g[n * 6 + 4], g5 = s_g[n * 6 + 5];
        float a = 0.f;
        #pragma unroll
        for (int i = 0; i < 10; i++) {
            const float mij =
                g0 * M[        i * 10 + jj] +
                g1 * M[100 +   i * 10 + jj] +
                g2 * M[200 +   i * 10 + jj] +
                g3 * M[300 +   i * 10 + jj] +
                g4 * M[400 +   i * 10 + jj] +
                g5 * M[500 +   i * 10 + jj];
            a += __shfl_sync(0xffffffff, st, i) * mij;
        }
        st = a;
    }
    if (tid < 10) out[STATE_BASE + b * 10 + tid] = st;
}

// ---------------------------------------------------------------------------
extern "C" void kernel_launch(void* const* d_in, const int* in_sizes, int n_in,
                              void* d_out, int out_size)
{
    const float* seq   = (const float*)d_in[0];
    const float* c1w   = (const float*)d_in[1];
    const float* c1b   = (const float*)d_in[2];
    const float* c2w   = (const float*)d_in[3];
    const float* c2b   = (const float*)d_in[4];
    const float* c3w   = (const float*)d_in[5];
    const float* c3b   = (const float*)d_in[6];
    const float* dw    = (const float*)d_in[7];
    const float* db    = (const float*)d_in[8];
    const float* trans = (const float*)d_in[9];
    float* out = (float*)d_out;

    cnn_kernel<<<NIMG, 256>>>(seq, c1w, c1b, c2w, c2b, c3w, c3b, dw, db, out);
    sfa_kernel<<<BATCH, 32>>>(trans, out);
}

// round 3
// speedup vs baseline: 1.5508x; 1.4422x over previous
#include <cuda_runtime.h>
#include <math.h>

#define BATCH 256
#define NSTEP 32
#define NIMG  (BATCH*NSTEP)

// Output layout (float32):
//   [0, 81920)        all_cnn_preds   (32,256,10)
//   [81920, 131072)   all_guard_preds (32,256,6)
//   [131072, 133632)  state_final     (256,10)
#define GUARD_BASE 81920
#define STATE_BASE 131072

__device__ float g_M[600];   // (6,10,10) transition matrices

// ---------------------------------------------------------------------------
// Fused CNN, 2 images per CTA, 256 threads.
// ---------------------------------------------------------------------------
__global__ __launch_bounds__(256, 3) void cnn_kernel(
    const float* __restrict__ seq,
    const float* __restrict__ c1w, const float* __restrict__ c1b,
    const float* __restrict__ c2w, const float* __restrict__ c2b,
    const float* __restrict__ c3w, const float* __restrict__ c3b,
    const float* __restrict__ dw,  const float* __restrict__ db,
    float* __restrict__ out)
{
    __shared__ __align__(16) float s_img[2][784];
    __shared__ __align__(16) float s1p[2][8 * 13 * 14];   // rows padded to 14
    __shared__ __align__(16) float s2[2][400];            // 16x5x5
    __shared__ float s3[2][32];
    __shared__ __align__(16) float s_w1p[8 * 12];
    __shared__ float s_b1[8];
    __shared__ __align__(16) float s_w2p[16 * 8 * 12];
    __shared__ float s_b2[16];
    __shared__ float s_w3t[16 * 9 * 32];   // [ic][k][oc] — lane-consecutive
    __shared__ float s_b3[32];
    __shared__ float s_dwT[32 * 10];       // [k][j]
    __shared__ float s_db[10];
    __shared__ float s_logits[2][10];
    __shared__ float s_p[2][10];

    const int tid = threadIdx.x;

    // ---- stage inputs: 2 images, float4 coalesced ----
    {
        const int img0 = blockIdx.x * 2;
        for (int k = tid; k < 392; k += 256) {          // 2 * 196 float4
            const int im = k / 196, q = k - im * 196;
            const int img = img0 + im;
            const int n = img >> 8, b = img & 255;
            const float4 v = ((const float4*)(seq + ((long)b * NSTEP + n) * 784))[q];
            ((float4*)s_img[im])[q] = v;
        }
    }
    if (tid < 8) {
        s_b1[tid] = c1b[tid];
        #pragma unroll
        for (int t = 0; t < 9; t++) s_w1p[tid * 12 + t] = c1w[tid * 9 + t];
    }
    if (tid < 128) {
        #pragma unroll
        for (int t = 0; t < 9; t++) s_w2p[tid * 12 + t] = c2w[tid * 9 + t];
    }
    if (tid < 16) s_b2[tid] = c2b[tid];
    for (int k = tid; k < 512; k += 256) {              // (oc,ic) pairs, transpose
        const int oc = k >> 4, ic = k & 15;
        #pragma unroll
        for (int t = 0; t < 9; t++) s_w3t[(ic * 9 + t) * 32 + oc] = c3w[k * 9 + t];
    }
    if (tid < 32) s_b3[tid] = c3b[tid];
    for (int k = tid; k < 320; k += 256)                // transpose dense weights
        s_dwT[(k & 31) * 10 + (k >> 5)] = dw[k];
    if (tid < 10) s_db[tid] = db[tid];
    __syncthreads();

    // ---- Stage 1: conv1 + relu + pool, sliding window ----
    // 16 groups (2 img x 8 ch) x 16 lanes; lane = output row y (13 used)
    {
        const int g  = tid >> 4;
        const int y  = tid & 15;
        const int im = g >> 3;
        const int c  = g & 7;
        if (y < 13) {
            const float4 w0 = *(const float4*)&s_w1p[c * 12];
            const float4 w1 = *(const float4*)&s_w1p[c * 12 + 4];
            const float w8  = s_w1p[c * 12 + 8];
            const float w[9] = {w0.x, w0.y, w0.z, w0.w, w1.x, w1.y, w1.z, w1.w, w8};
            const float bias = s_b1[c];
            const int iy = 2 * y;

            float win[4][4];
            #pragma unroll
            for (int r = 0; r < 4; r++) {
                const float2 a = *(const float2*)&s_img[im][(iy + r) * 28];
                const float2 d = *(const float2*)&s_img[im][(iy + r) * 28 + 2];
                win[r][0] = a.x; win[r][1] = a.y; win[r][2] = d.x; win[r][3] = d.y;
            }
            #pragma unroll
            for (int x = 0; x < 13; x++) {
                float acc = 0.f;
                #pragma unroll
                for (int dy = 0; dy < 2; dy++)
                    #pragma unroll
                    for (int dx = 0; dx < 2; dx++) {
                        float v = bias;
                        #pragma unroll
                        for (int ky = 0; ky < 3; ky++)
                            #pragma unroll
                            for (int kx = 0; kx < 3; kx++)
                                v += win[dy + ky][dx + kx] * w[ky * 3 + kx];
                        acc += fmaxf(v, 0.f);
                    }
                s1p[im][c * 182 + y * 14 + x] = acc * 0.25f;
                if (x < 12) {
                    #pragma unroll
                    for (int r = 0; r < 4; r++) {
                        win[r][0] = win[r][2]; win[r][1] = win[r][3];
                        const float2 nb = *(const float2*)&s_img[im][(iy + r) * 28 + 2 * x + 4];
                        win[r][2] = nb.x; win[r][3] = nb.y;
                    }
                }
            }
        }
    }
    __syncthreads();

    // ---- Stage 2: conv2 + relu + pool, 4-oc blocking. 200 threads ----
    if (tid < 200) {
        const int im  = tid / 100;
        const int r2  = tid - im * 100;
        const int ocg = r2 / 25;
        const int pos = r2 - ocg * 25;
        const int y = pos / 5, x = pos - y * 5;
        const int iy = 2 * y, ix = 2 * x;

        float acc[4][4];
        #pragma unroll
        for (int o = 0; o < 4; o++) {
            const float bb = s_b2[ocg * 4 + o];
            acc[o][0] = bb; acc[o][1] = bb; acc[o][2] = bb; acc[o][3] = bb;
        }
        #pragma unroll
        for (int ic = 0; ic < 8; ic++) {
            float win[4][4];
            #pragma unroll
            for (int r = 0; r < 4; r++) {
                const float2 u = *(const float2*)&s1p[im][ic * 182 + (iy + r) * 14 + ix];
                const float2 v = *(const float2*)&s1p[im][ic * 182 + (iy + r) * 14 + ix + 2];
                win[r][0] = u.x; win[r][1] = u.y; win[r][2] = v.x; win[r][3] = v.y;
            }
            #pragma unroll
            for (int o = 0; o < 4; o++) {
                const int oc = ocg * 4 + o;
                const float4 u0 = *(const float4*)&s_w2p[(oc * 8 + ic) * 12];
                const float4 u1 = *(const float4*)&s_w2p[(oc * 8 + ic) * 12 + 4];
                const float u8  = s_w2p[(oc * 8 + ic) * 12 + 8];
                const float w[9] = {u0.x, u0.y, u0.z, u0.w, u1.x, u1.y, u1.z, u1.w, u8};
                #pragma unroll
                for (int ky = 0; ky < 3; ky++)
                    #pragma unroll
                    for (int kx = 0; kx < 3; kx++) {
                        const float ww = w[ky * 3 + kx];
                        acc[o][0] += win[ky    ][kx    ] * ww;
                        acc[o][1] += win[ky    ][kx + 1] * ww;
                        acc[o][2] += win[ky + 1][kx    ] * ww;
                        acc[o][3] += win[ky + 1][kx + 1] * ww;
                    }
            }
        }
        #pragma unroll
        for (int o = 0; o < 4; o++)
            s2[im][(ocg * 4 + o) * 25 + pos] =
                0.25f * (fmaxf(acc[o][0], 0.f) + fmaxf(acc[o][1], 0.f) +
                         fmaxf(acc[o][2], 0.f) + fmaxf(acc[o][3], 0.f));
    }
    __syncthreads();

    // ---- Stage 3: conv3 + relu + pool. 64 threads: (img, oc) ----
    if (tid < 64) {
        const int im = tid >> 5;
        const int oc = tid & 31;
        float v0 = s_b3[oc], v1 = v0, v2 = v0, v3 = v0;
        #pragma unroll
        for (int ic = 0; ic < 16; ic++) {
            float win[4][4];
            #pragma unroll
            for (int r = 0; r < 4; r++)
                #pragma unroll
                for (int cc = 0; cc < 4; cc++)
                    win[r][cc] = s2[im][ic * 25 + r * 5 + cc];   // broadcast
            float w[9];
            #pragma unroll
            for (int k = 0; k < 9; k++)
                w[k] = s_w3t[(ic * 9 + k) * 32 + oc];            // conflict-free
            #pragma unroll
            for (int ky = 0; ky < 3; ky++)
                #pragma unroll
                for (int kx = 0; kx < 3; kx++) {
                    const float ww = w[ky * 3 + kx];
                    v0 += win[ky    ][kx    ] * ww;
                    v1 += win[ky    ][kx + 1] * ww;
                    v2 += win[ky + 1][kx    ] * ww;
                    v3 += win[ky + 1][kx + 1] * ww;
                }
        }
        s3[im][oc] = 0.25f * (fmaxf(v0, 0.f) + fmaxf(v1, 0.f) +
                              fmaxf(v2, 0.f) + fmaxf(v3, 0.f));
    }
    __syncthreads();

    // ---- Dense(32->10): 20 threads ----
    if (tid < 20) {
        const int im = tid / 10, j = tid - im * 10;
        float v = s_db[j];
        #pragma unroll
        for (int k = 0; k < 32; k++) v += s3[im][k] * s_dwT[k * 10 + j];
        s_logits[im][j] = v;
    }
    __syncthreads();
    if (tid < 20) {
        const int im = tid / 10, j = tid - im * 10;
        float m = s_logits[im][0];
        #pragma unroll
        for (int k = 1; k < 10; k++) m = fmaxf(m, s_logits[im][k]);
        float sum = 0.f;
        #pragma unroll
        for (int k = 0; k < 10; k++) sum += __expf(s_logits[im][k] - m);
        const float p = __expf(s_logits[im][j] - m) / sum;
        s_p[im][j] = p;
        out[(blockIdx.x * 2 + im) * 10 + j] = p;
    }
    __syncthreads();
    if (tid < 12) {
        const int im = tid / 6, j = tid - im * 6;
        const float* p = s_p[im];
        float g;
        switch (j) {
            case 0:  g = p[8];         break;
            case 1:  g = p[4] + p[6];  break;
            case 2:  g = p[0] + p[2];  break;
            case 3:  g = p[7] + p[9];  break;
            case 4:  g = p[5];         break;
            default: g = p[1] + p[3];  break;
        }
        out[GUARD_BASE + (blockIdx.x * 2 + im) * 6 + j] = g;
    }
}

// ---------------------------------------------------------------------------
// Prep: M = softmax(trans/0.1) with fixed accepting row -> g_M (once).
// ---------------------------------------------------------------------------
__global__ __launch_bounds__(64) void prep_kernel(const float* __restrict__ trans)
{
    const int tid = threadIdx.x;
    if (tid < 54) {
        const int r = tid / 9, i = tid - r * 9;
        const float* tp = trans + (r * 9 + i) * 10;
        float m = tp[0] * 10.f;
        #pragma unroll
        for (int j = 1; j < 10; j++) m = fmaxf(m, tp[j] * 10.f);
        float e[10];
        float s = 0.f;
        #pragma unroll
        for (int j = 0; j < 10; j++) { e[j] = __expf(tp[j] * 10.f - m); s += e[j]; }
        const float inv = 1.f / s;
        #pragma unroll
        for (int j = 0; j < 10; j++) g_M[r * 100 + i * 10 + j] = e[j] * inv;
    } else if (tid < 60) {
        const int r = tid - 54;
        #pragma unroll
        for (int j = 0; j < 10; j++) g_M[r * 100 + 90 + j] = (j == 9) ? 1.f : 0.f;
    }
}

// ---------------------------------------------------------------------------
// SFA: one warp per batch element. M column held in registers, state via shfl.
// ---------------------------------------------------------------------------
__global__ __launch_bounds__(32) void sfa_kernel(float* __restrict__ out)
{
    __shared__ float s_g[NSTEP * 6];

    const int tid = threadIdx.x;
    const int b   = blockIdx.x;

    const float* gbase = out + GUARD_BASE;
    for (int k = tid; k < NSTEP * 6; k += 32) {
        const int n = k / 6, j = k - n * 6;
        s_g[k] = gbase[(n * BATCH + b) * 6 + j];
    }

    const int jj = (tid < 10) ? tid : 0;
    float Mr[6][10];
    #pragma unroll
    for (int r = 0; r < 6; r++)
        #pragma unroll
        for (int i = 0; i < 10; i++)
            Mr[r][i] = g_M[r * 100 + i * 10 + jj];
    __syncthreads();

    float st = (tid == 0) ? 1.f : 0.f;
    for (int n = 0; n < NSTEP; n++) {
        const float g0 = s_g[n * 6 + 0], g1 = s_g[n * 6 + 1], g2 = s_g[n * 6 + 2];
        const float g3 = s_g[n * 6 + 3], g4 = s_g[n * 6 + 4], g5 = s_g[n * 6 + 5];
        float a = 0.f;
        #pragma unroll
        for (int i = 0; i < 10; i++) {
            const float si = __shfl_sync(0xffffffff, st, i);
            const float mij = g0 * Mr[0][i] + g1 * Mr[1][i] + g2 * Mr[2][i]
                            + g3 * Mr[3][i] + g4 * Mr[4][i] + g5 * Mr[5][i];
            a += si * mij;
        }
        st = a;
    }
    if (tid < 10) out[STATE_BASE + b * 10 + tid] = st;
}

// ---------------------------------------------------------------------------
extern "C" void kernel_launch(void* const* d_in, const int* in_sizes, int n_in,
                              void* d_out, int out_size)
{
    const float* seq   = (const float*)d_in[0];
    const float* c1w   = (const float*)d_in[1];
    const float* c1b   = (const float*)d_in[2];
    const float* c2w   = (const float*)d_in[3];
    const float* c2b   = (const float*)d_in[4];
    const float* c3w   = (const float*)d_in[5];
    const float* c3b   = (const float*)d_in[6];
    const float* dw    = (const float*)d_in[7];
    const float* db    = (const float*)d_in[8];
    const float* trans = (const float*)d_in[9];
    float* out = (float*)d_out;

    prep_kernel<<<1, 64>>>(trans);
    cnn_kernel<<<NIMG / 2, 256>>>(seq, c1w, c1b, c2w, c2b, c3w, c3b, dw, db, out);
    sfa_kernel<<<BATCH, 32>>>(out);
}

// round 5
// speedup vs baseline: 1.6993x; 1.0957x over previous
#include <cuda_runtime.h>
#include <math.h>

#define BATCH 256
#define NSTEP 32
#define NIMG  (BATCH*NSTEP)

// Output layout (float32):
//   [0, 81920)        all_cnn_preds   (32,256,10)
//   [81920, 131072)   all_guard_preds (32,256,6)
//   [131072, 133632)  state_final     (256,10)
#define GUARD_BASE 81920
#define STATE_BASE 131072

#define IMG_STRIDE 30          // 28 cols padded -> 2-way max bank conflicts
#define S1_STRIDE  22          // 13 cols padded -> 2-way max (25-lane window reads)
#define S1_PLANE   (13 * S1_STRIDE)   // 286

__device__ float g_M[600];     // (6,10,10) transition matrices

struct SmemLayout {
    float img[2][28 * IMG_STRIDE];      // 2 x 840
    float s1p[2][8 * S1_PLANE];         // 2 x 2288
    float s2[2][400];
    float s3[2][32];
    float w1p[8 * 12];  float b1[8];
    float w2p[16 * 8 * 12]; float b2[16];
    float w3t[16 * 9 * 32]; float b3[32];
    float dwT[32 * 10]; float db[10];
    float logits[2][10]; float p2[2][10];
};

// ---------------------------------------------------------------------------
// Fused CNN, 2 images per CTA, 256 threads, dynamic smem, occ-4.
// ---------------------------------------------------------------------------
__global__ __launch_bounds__(256, 4) void cnn_kernel(
    const float* __restrict__ seq,
    const float* __restrict__ c1w, const float* __restrict__ c1b,
    const float* __restrict__ c2w, const float* __restrict__ c2b,
    const float* __restrict__ c3w, const float* __restrict__ c3b,
    const float* __restrict__ dw,  const float* __restrict__ db,
    const float* __restrict__ trans,
    float* __restrict__ out)
{
    extern __shared__ __align__(16) char smem_raw[];
    SmemLayout* S = (SmemLayout*)smem_raw;

    const int tid = threadIdx.x;

    // ---- prep: block 0 computes transition matrices (replaces prep kernel)
    if (blockIdx.x == 0 && tid < 60) {
        if (tid < 54) {
            const int r = tid / 9, i = tid - r * 9;
            const float* tp = trans + (r * 9 + i) * 10;
            float m = tp[0] * 10.f;
            #pragma unroll
            for (int j = 1; j < 10; j++) m = fmaxf(m, tp[j] * 10.f);
            float e[10];
            float s = 0.f;
            #pragma unroll
            for (int j = 0; j < 10; j++) { e[j] = __expf(tp[j] * 10.f - m); s += e[j]; }
            const float inv = 1.f / s;
            #pragma unroll
            for (int j = 0; j < 10; j++) g_M[r * 100 + i * 10 + j] = e[j] * inv;
        } else {
            const int r = tid - 54;
            #pragma unroll
            for (int j = 0; j < 10; j++) g_M[r * 100 + 90 + j] = (j == 9) ? 1.f : 0.f;
        }
    }

    // ---- stage inputs: 2 images as float2 into stride-30 rows ----
    {
        const int img0 = blockIdx.x * 2;
        for (int k = tid; k < 784; k += 256) {       // 2 * 392 float2
            const int im = k / 392, q = k - im * 392;
            const int img = img0 + im;
            const int n = img >> 8, b = img & 255;
            const float2 v = ((const float2*)(seq + ((long)b * NSTEP + n) * 784))[q];
            const int row = q / 14, col2 = q - row * 14;
            *(float2*)&S->img[im][row * IMG_STRIDE + col2 * 2] = v;
        }
    }
    if (tid < 8) {
        S->b1[tid] = c1b[tid];
        #pragma unroll
        for (int t = 0; t < 9; t++) S->w1p[tid * 12 + t] = c1w[tid * 9 + t];
    }
    if (tid < 128) {
        #pragma unroll
        for (int t = 0; t < 9; t++) S->w2p[tid * 12 + t] = c2w[tid * 9 + t];
    }
    if (tid < 16) S->b2[tid] = c2b[tid];
    for (int k = tid; k < 512; k += 256) {           // transpose conv3 weights
        const int oc = k >> 4, ic = k & 15;
        #pragma unroll
        for (int t = 0; t < 9; t++) S->w3t[(ic * 9 + t) * 32 + oc] = c3w[k * 9 + t];
    }
    if (tid < 32) S->b3[tid] = c3b[tid];
    for (int k = tid; k < 320; k += 256)
        S->dwT[(k & 31) * 10 + (k >> 5)] = dw[k];
    if (tid < 10) S->db[tid] = db[tid];
    __syncthreads();

    // ---- Stage 1: conv1 + relu + pool, sliding window ----
    {
        const int g  = tid >> 4;
        const int y  = tid & 15;
        const int im = g >> 3;
        const int c  = g & 7;
        if (y < 13) {
            const float4 w0 = *(const float4*)&S->w1p[c * 12];
            const float4 w1 = *(const float4*)&S->w1p[c * 12 + 4];
            const float w8  = S->w1p[c * 12 + 8];
            const float w[9] = {w0.x, w0.y, w0.z, w0.w, w1.x, w1.y, w1.z, w1.w, w8};
            const float bias = S->b1[c];
            const int iy = 2 * y;

            float win[4][4];
            #pragma unroll
            for (int r = 0; r < 4; r++) {
                const float2 a = *(const float2*)&S->img[im][(iy + r) * IMG_STRIDE];
                const float2 d = *(const float2*)&S->img[im][(iy + r) * IMG_STRIDE + 2];
                win[r][0] = a.x; win[r][1] = a.y; win[r][2] = d.x; win[r][3] = d.y;
            }
            #pragma unroll
            for (int x = 0; x < 13; x++) {
                float acc = 0.f;
                #pragma unroll
                for (int dy = 0; dy < 2; dy++)
                    #pragma unroll
                    for (int dx = 0; dx < 2; dx++) {
                        float v = bias;
                        #pragma unroll
                        for (int ky = 0; ky < 3; ky++)
                            #pragma unroll
                            for (int kx = 0; kx < 3; kx++)
                                v += win[dy + ky][dx + kx] * w[ky * 3 + kx];
                        acc += fmaxf(v, 0.f);
                    }
                S->s1p[im][c * S1_PLANE + y * S1_STRIDE + x] = acc * 0.25f;
                if (x < 12) {
                    #pragma unroll
                    for (int r = 0; r < 4; r++) {
                        win[r][0] = win[r][2]; win[r][1] = win[r][3];
                        const float2 nb = *(const float2*)
                            &S->img[im][(iy + r) * IMG_STRIDE + 2 * x + 4];
                        win[r][2] = nb.x; win[r][3] = nb.y;
                    }
                }
            }
        }
    }
    __syncthreads();

    // ---- Stage 2: conv2 + relu + pool, 4-oc blocking. 200 threads ----
    if (tid < 200) {
        const int im  = tid / 100;
        const int r2  = tid - im * 100;
        const int ocg = r2 / 25;
        const int pos = r2 - ocg * 25;
        const int y = pos / 5, x = pos - y * 5;
        const int iy = 2 * y, ix = 2 * x;

        float acc[4][4];
        #pragma unroll
        for (int o = 0; o < 4; o++) {
            const float bb = S->b2[ocg * 4 + o];
            acc[o][0] = bb; acc[o][1] = bb; acc[o][2] = bb; acc[o][3] = bb;
        }
        #pragma unroll
        for (int ic = 0; ic < 8; ic++) {
            float win[4][4];
            #pragma unroll
            for (int r = 0; r < 4; r++) {
                const float* rowp = &S->s1p[im][ic * S1_PLANE + (iy + r) * S1_STRIDE + ix];
                const float2 u = *(const float2*)rowp;
                const float2 v = *(const float2*)(rowp + 2);
                win[r][0] = u.x; win[r][1] = u.y; win[r][2] = v.x; win[r][3] = v.y;
            }
            #pragma unroll
            for (int o = 0; o < 4; o++) {
                const int oc = ocg * 4 + o;
                const float4 u0 = *(const float4*)&S->w2p[(oc * 8 + ic) * 12];
                const float4 u1 = *(const float4*)&S->w2p[(oc * 8 + ic) * 12 + 4];
                const float u8  = S->w2p[(oc * 8 + ic) * 12 + 8];
                const float w[9] = {u0.x, u0.y, u0.z, u0.w, u1.x, u1.y, u1.z, u1.w, u8};
                #pragma unroll
                for (int ky = 0; ky < 3; ky++)
                    #pragma unroll
                    for (int kx = 0; kx < 3; kx++) {
                        const float ww = w[ky * 3 + kx];
                        acc[o][0] += win[ky    ][kx    ] * ww;
                        acc[o][1] += win[ky    ][kx + 1] * ww;
                        acc[o][2] += win[ky + 1][kx    ] * ww;
                        acc[o][3] += win[ky + 1][kx + 1] * ww;
                    }
            }
        }
        #pragma unroll
        for (int o = 0; o < 4; o++)
            S->s2[im][(ocg * 4 + o) * 25 + pos] =
                0.25f * (fmaxf(acc[o][0], 0.f) + fmaxf(acc[o][1], 0.f) +
                         fmaxf(acc[o][2], 0.f) + fmaxf(acc[o][3], 0.f));
    }
    __syncthreads();

    // ---- Stage 3: conv3 + relu + pool. 64 threads: (img, oc) ----
    if (tid < 64) {
        const int im = tid >> 5;
        const int oc = tid & 31;
        float v0 = S->b3[oc], v1 = v0, v2 = v0, v3 = v0;
        #pragma unroll
        for (int ic = 0; ic < 16; ic++) {
            float win[4][4];
            #pragma unroll
            for (int r = 0; r < 4; r++)
                #pragma unroll
                for (int cc = 0; cc < 4; cc++)
                    win[r][cc] = S->s2[im][ic * 25 + r * 5 + cc];   // broadcast
            float w[9];
            #pragma unroll
            for (int k = 0; k < 9; k++)
                w[k] = S->w3t[(ic * 9 + k) * 32 + oc];              // conflict-free
            #pragma unroll
            for (int ky = 0; ky < 3; ky++)
                #pragma unroll
                for (int kx = 0; kx < 3; kx++) {
                    const float ww = w[ky * 3 + kx];
                    v0 += win[ky    ][kx    ] * ww;
                    v1 += win[ky    ][kx + 1] * ww;
                    v2 += win[ky + 1][kx    ] * ww;
                    v3 += win[ky + 1][kx + 1] * ww;
                }
        }
        S->s3[im][oc] = 0.25f * (fmaxf(v0, 0.f) + fmaxf(v1, 0.f) +
                                 fmaxf(v2, 0.f) + fmaxf(v3, 0.f));
    }
    __syncthreads();

    // ---- Dense + softmax + guards: warp 0 only, __syncwarp ordering ----
    if (tid < 32) {
        if (tid < 20) {
            const int im = tid / 10, j = tid - im * 10;
            float v = S->db[j];
            #pragma unroll
            for (int k = 0; k < 32; k++) v += S->s3[im][k] * S->dwT[k * 10 + j];
            S->logits[im][j] = v;
        }
        __syncwarp();
        if (tid < 20) {
            const int im = tid / 10, j = tid - im * 10;
            float m = S->logits[im][0];
            #pragma unroll
            for (int k = 1; k < 10; k++) m = fmaxf(m, S->logits[im][k]);
            float sum = 0.f;
            #pragma unroll
            for (int k = 0; k < 10; k++) sum += __expf(S->logits[im][k] - m);
            const float p = __expf(S->logits[im][j] - m) / sum;
            S->p2[im][j] = p;
            out[(blockIdx.x * 2 + im) * 10 + j] = p;
        }
        __syncwarp();
        if (tid < 12) {
            const int im = tid / 6, j = tid - im * 6;
            const float* p = S->p2[im];
            float g;
            switch (j) {
                case 0:  g = p[8];         break;
                case 1:  g = p[4] + p[6];  break;
                case 2:  g = p[0] + p[2];  break;
                case 3:  g = p[7] + p[9];  break;
                case 4:  g = p[5];         break;
                default: g = p[1] + p[3];  break;
            }
            out[GUARD_BASE + (blockIdx.x * 2 + im) * 6 + j] = g;
        }
    }
}

// ---------------------------------------------------------------------------
// SFA: one warp per batch element. M column in registers, state via shfl.
// ---------------------------------------------------------------------------
__global__ __launch_bounds__(32) void sfa_kernel(float* __restrict__ out)
{
    __shared__ float s_g[NSTEP * 6];

    const int tid = threadIdx.x;
    const int b   = blockIdx.x;

    const float* gbase = out + GUARD_BASE;
    for (int k = tid; k < NSTEP * 6; k += 32) {
        const int n = k / 6, j = k - n * 6;
        s_g[k] = gbase[(n * BATCH + b) * 6 + j];
    }

    const int jj = (tid < 10) ? tid : 0;
    float Mr[6][10];
    #pragma unroll
    for (int r = 0; r < 6; r++)
        #pragma unroll
        for (int i = 0; i < 10; i++)
            Mr[r][i] = g_M[r * 100 + i * 10 + jj];
    __syncthreads();

    float st = (tid == 0) ? 1.f : 0.f;
    for (int n = 0; n < NSTEP; n++) {
        const float g0 = s_g[n * 6 + 0], g1 = s_g[n * 6 + 1], g2 = s_g[n * 6 + 2];
        const float g3 = s_g[n * 6 + 3], g4 = s_g[n * 6 + 4], g5 = s_g[n * 6 + 5];
        float a = 0.f;
        #pragma unroll
        for (int i = 0; i < 10; i++) {
            const float si = __shfl_sync(0xffffffff, st, i);
            const float mij = g0 * Mr[0][i] + g1 * Mr[1][i] + g2 * Mr[2][i]
                            + g3 * Mr[3][i] + g4 * Mr[4][i] + g5 * Mr[5][i];
            a += si * mij;
        }
        st = a;
    }
    if (tid < 10) out[STATE_BASE + b * 10 + tid] = st;
}

// ---------------------------------------------------------------------------
extern "C" void kernel_launch(void* const* d_in, const int* in_sizes, int n_in,
                              void* d_out, int out_size)
{
    const float* seq   = (const float*)d_in[0];
    const float* c1w   = (const float*)d_in[1];
    const float* c1b   = (const float*)d_in[2];
    const float* c2w   = (const float*)d_in[3];
    const float* c2b   = (const float*)d_in[4];
    const float* c3w   = (const float*)d_in[5];
    const float* c3b   = (const float*)d_in[6];
    const float* dw    = (const float*)d_in[7];
    const float* db    = (const float*)d_in[8];
    const float* trans = (const float*)d_in[9];
    float* out = (float*)d_out;

    const int smem_bytes = (int)sizeof(SmemLayout);
    static int attr_done = 0;
    // Setting a func attribute is idempotent and not a captured op.
    cudaFuncSetAttribute(cnn_kernel, cudaFuncAttributeMaxDynamicSharedMemorySize,
                         smem_bytes);
    (void)attr_done;

    cnn_kernel<<<NIMG / 2, 256, smem_bytes>>>(seq, c1w, c1b, c2w, c2b,
                                              c3w, c3b, dw, db, trans, out);
    sfa_kernel<<<BATCH, 32>>>(out);
}

// round 6
// speedup vs baseline: 1.7748x; 1.0444x over previous
#include <cuda_runtime.h>
#include <math.h>

#define BATCH 256
#define NSTEP 32
#define NIMG  (BATCH*NSTEP)

#define GUARD_BASE 81920
#define STATE_BASE 131072

#define IMG_STRIDE 30
#define S1_STRIDE  22
#define S1_PLANE   (13 * S1_STRIDE)

typedef unsigned long long u64t;

// packed f32x2 helpers (sm_103a FFMA2 path)
#define PACK2(d, lo, hi) \
    asm("mov.b64 %0, {%1, %2};" : "=l"(d) : "r"(__float_as_uint(lo)), "r"(__float_as_uint(hi)))
#define FMA2(d, a, b, c) \
    asm("fma.rn.f32x2 %0, %1, %2, %3;" : "=l"(d) : "l"(a), "l"(b), "l"(c))
#define UNPACK2(lo, hi, s) do { unsigned _ulo, _uhi; \
    asm("mov.b64 {%0, %1}, %2;" : "=r"(_ulo), "=r"(_uhi) : "l"(s)); \
    lo = __uint_as_float(_ulo); hi = __uint_as_float(_uhi); } while (0)

__device__ float g_M[600];     // (6,10,10) transition matrices

struct SmemLayout {
    float img[2][28 * IMG_STRIDE];
    float s1p[2][8 * S1_PLANE];
    float s2[2][400];
    float s3[2][32];
    float w1p[8 * 12];  float b1[8];
    float w2pk[8 * 8 * 20];      // [ocpair][ic][k*2+half], padded to 20
    float b2[16];
    float w3pk[8 * 9 * 32 * 2];  // [icpair][k][oc] float2 (ic even, ic odd)
    float b3[32];
    float dwT[32 * 10]; float db[10];
    float logits[2][10]; float p2[2][10];
};

// ---------------------------------------------------------------------------
// Fused CNN, 2 images per CTA, 256 threads, FFMA2 throughout.
// ---------------------------------------------------------------------------
__global__ __launch_bounds__(256, 4) void cnn_kernel(
    const float* __restrict__ seq,
    const float* __restrict__ c1w, const float* __restrict__ c1b,
    const float* __restrict__ c2w, const float* __restrict__ c2b,
    const float* __restrict__ c3w, const float* __restrict__ c3b,
    const float* __restrict__ dw,  const float* __restrict__ db,
    const float* __restrict__ trans,
    float* __restrict__ out)
{
    extern __shared__ __align__(16) char smem_raw[];
    SmemLayout* S = (SmemLayout*)smem_raw;

    const int tid = threadIdx.x;

    // ---- prep (block 0): transition matrices into g_M ----
    if (blockIdx.x == 0 && tid < 60) {
        if (tid < 54) {
            const int r = tid / 9, i = tid - r * 9;
            const float* tp = trans + (r * 9 + i) * 10;
            float m = tp[0] * 10.f;
            #pragma unroll
            for (int j = 1; j < 10; j++) m = fmaxf(m, tp[j] * 10.f);
            float e[10];
            float s = 0.f;
            #pragma unroll
            for (int j = 0; j < 10; j++) { e[j] = __expf(tp[j] * 10.f - m); s += e[j]; }
            const float inv = 1.f / s;
            #pragma unroll
            for (int j = 0; j < 10; j++) g_M[r * 100 + i * 10 + j] = e[j] * inv;
        } else {
            const int r = tid - 54;
            #pragma unroll
            for (int j = 0; j < 10; j++) g_M[r * 100 + 90 + j] = (j == 9) ? 1.f : 0.f;
        }
    }

    // ---- stage inputs ----
    {
        const int img0 = blockIdx.x * 2;
        for (int k = tid; k < 784; k += 256) {
            const int im = k / 392, q = k - im * 392;
            const int img = img0 + im;
            const int n = img >> 8, b = img & 255;
            const float2 v = ((const float2*)(seq + ((long)b * NSTEP + n) * 784))[q];
            const int row = q / 14, col2 = q - row * 14;
            *(float2*)&S->img[im][row * IMG_STRIDE + col2 * 2] = v;
        }
    }
    if (tid < 8) {
        S->b1[tid] = c1b[tid];
        #pragma unroll
        for (int t = 0; t < 9; t++) S->w1p[tid * 12 + t] = c1w[tid * 9 + t];
    }
    if (tid < 128) {   // conv2 weights -> oc-pair packed
        const int oc = tid >> 3, ic = tid & 7;
        #pragma unroll
        for (int t = 0; t < 9; t++)
            S->w2pk[((oc >> 1) * 8 + ic) * 20 + t * 2 + (oc & 1)] = c2w[tid * 9 + t];
    }
    if (tid < 16) S->b2[tid] = c2b[tid];
    for (int k = tid; k < 512; k += 256) {   // conv3 weights -> ic-pair packed
        const int oc = k >> 4, ic = k & 15;
        #pragma unroll
        for (int t = 0; t < 9; t++)
            S->w3pk[(((ic >> 1) * 9 + t) * 32 + oc) * 2 + (ic & 1)] = c3w[k * 9 + t];
    }
    if (tid < 32) S->b3[tid] = c3b[tid];
    for (int k = tid; k < 320; k += 256)
        S->dwT[(k & 31) * 10 + (k >> 5)] = dw[k];
    if (tid < 10) S->db[tid] = db[tid];
    __syncthreads();

    // ---- Stage 1: conv1 + relu + pool (FFMA2 packed along pool-dx) ----
    {
        const int g  = tid >> 4;
        const int y  = tid & 15;
        const int im = g >> 3;
        const int c  = g & 7;
        if (y < 13) {
            const float4 w0 = *(const float4*)&S->w1p[c * 12];
            const float4 w1 = *(const float4*)&S->w1p[c * 12 + 4];
            const float w8s = S->w1p[c * 12 + 8];
            const float ws[9] = {w0.x, w0.y, w0.z, w0.w, w1.x, w1.y, w1.z, w1.w, w8s};
            u64t W2[9];
            #pragma unroll
            for (int k = 0; k < 9; k++) PACK2(W2[k], ws[k], ws[k]);
            const float bias = S->b1[c];
            u64t B2; PACK2(B2, bias, bias);
            const int iy = 2 * y;

            float win[4][4];
            #pragma unroll
            for (int r = 0; r < 4; r++) {
                const float2 a = *(const float2*)&S->img[im][(iy + r) * IMG_STRIDE];
                const float2 d = *(const float2*)&S->img[im][(iy + r) * IMG_STRIDE + 2];
                win[r][0] = a.x; win[r][1] = a.y; win[r][2] = d.x; win[r][3] = d.y;
            }
            #pragma unroll
            for (int x = 0; x < 13; x++) {
                u64t a0 = B2, a1 = B2;   // (v00,v01), (v10,v11)
                #pragma unroll
                for (int ky = 0; ky < 3; ky++)
                    #pragma unroll
                    for (int kx = 0; kx < 3; kx++) {
                        u64t Pa, Pb;
                        PACK2(Pa, win[ky    ][kx], win[ky    ][kx + 1]);
                        PACK2(Pb, win[ky + 1][kx], win[ky + 1][kx + 1]);
                        FMA2(a0, Pa, W2[ky * 3 + kx], a0);
                        FMA2(a1, Pb, W2[ky * 3 + kx], a1);
                    }
                float v00, v01, v10, v11;
                UNPACK2(v00, v01, a0);
                UNPACK2(v10, v11, a1);
                S->s1p[im][c * S1_PLANE + y * S1_STRIDE + x] =
                    0.25f * (fmaxf(v00, 0.f) + fmaxf(v01, 0.f) +
                             fmaxf(v10, 0.f) + fmaxf(v11, 0.f));
                if (x < 12) {
                    #pragma unroll
                    for (int r = 0; r < 4; r++) {
                        win[r][0] = win[r][2]; win[r][1] = win[r][3];
                        const float2 nb = *(const float2*)
                            &S->img[im][(iy + r) * IMG_STRIDE + 2 * x + 4];
                        win[r][2] = nb.x; win[r][3] = nb.y;
                    }
                }
            }
        }
    }
    __syncthreads();

    // ---- Stage 2: conv2 + relu + pool (FFMA2 packed along oc-pairs) ----
    if (tid < 200) {
        const int im  = tid / 100;
        const int r2  = tid - im * 100;
        const int ocg = r2 / 25;
        const int pos = r2 - ocg * 25;
        const int y = pos / 5, x = pos - y * 5;
        const int iy = 2 * y, ix = 2 * x;
        const int op0 = ocg * 2, op1 = ocg * 2 + 1;

        u64t A[2][4];   // [ocpair][pos 00,01,10,11]
        {
            u64t B0, B1;
            PACK2(B0, S->b2[ocg * 4 + 0], S->b2[ocg * 4 + 1]);
            PACK2(B1, S->b2[ocg * 4 + 2], S->b2[ocg * 4 + 3]);
            #pragma unroll
            for (int p = 0; p < 4; p++) { A[0][p] = B0; A[1][p] = B1; }
        }
        #pragma unroll
        for (int ic = 0; ic < 8; ic++) {
            float win[4][4];
            #pragma unroll
            for (int r = 0; r < 4; r++) {
                const float* rowp = &S->s1p[im][ic * S1_PLANE + (iy + r) * S1_STRIDE + ix];
                const float2 u = *(const float2*)rowp;
                const float2 v = *(const float2*)(rowp + 2);
                win[r][0] = u.x; win[r][1] = u.y; win[r][2] = v.x; win[r][3] = v.y;
            }
            const u64t* wq0 = (const u64t*)&S->w2pk[(op0 * 8 + ic) * 20];
            const u64t* wq1 = (const u64t*)&S->w2pk[(op1 * 8 + ic) * 20];
            #pragma unroll
            for (int ky = 0; ky < 3; ky++)
                #pragma unroll
                for (int kx = 0; kx < 3; kx++) {
                    const int k = ky * 3 + kx;
                    const u64t W0 = wq0[k], W1 = wq1[k];
                    u64t D00, D01, D10, D11;
                    PACK2(D00, win[ky    ][kx    ], win[ky    ][kx    ]);
                    PACK2(D01, win[ky    ][kx + 1], win[ky    ][kx + 1]);
                    PACK2(D10, win[ky + 1][kx    ], win[ky + 1][kx    ]);
                    PACK2(D11, win[ky + 1][kx + 1], win[ky + 1][kx + 1]);
                    FMA2(A[0][0], D00, W0, A[0][0]); FMA2(A[1][0], D00, W1, A[1][0]);
                    FMA2(A[0][1], D01, W0, A[0][1]); FMA2(A[1][1], D01, W1, A[1][1]);
                    FMA2(A[0][2], D10, W0, A[0][2]); FMA2(A[1][2], D10, W1, A[1][2]);
                    FMA2(A[0][3], D11, W0, A[0][3]); FMA2(A[1][3], D11, W1, A[1][3]);
                }
        }
        #pragma unroll
        for (int pr = 0; pr < 2; pr++) {
            float e0 = 0.f, e1 = 0.f;
            #pragma unroll
            for (int p = 0; p < 4; p++) {
                float lo, hi;
                UNPACK2(lo, hi, A[pr][p]);
                e0 += fmaxf(lo, 0.f);
                e1 += fmaxf(hi, 0.f);
            }
            S->s2[im][(ocg * 4 + 2 * pr    ) * 25 + pos] = 0.25f * e0;
            S->s2[im][(ocg * 4 + 2 * pr + 1) * 25 + pos] = 0.25f * e1;
        }
    }
    __syncthreads();

    // ---- Stage 3: conv3 + relu + pool. 256 threads (im,oc,pos), ic-pair FFMA2 ----
    {
        const int im  = tid >> 7;
        const int r3  = tid & 127;
        const int oc  = r3 >> 2;
        const int pos = r3 & 3;
        const int dy = pos >> 1, dx = pos & 1;

        u64t acc; PACK2(acc, 0.f, 0.f);
        #pragma unroll
        for (int icp = 0; icp < 8; icp++) {
            const float* pe = &S->s2[im][(2 * icp    ) * 25 + dy * 5 + dx];
            const float* po = &S->s2[im][(2 * icp + 1) * 25 + dy * 5 + dx];
            #pragma unroll
            for (int ky = 0; ky < 3; ky++)
                #pragma unroll
                for (int kx = 0; kx < 3; kx++) {
                    const int k = ky * 3 + kx;
                    const u64t W = *(const u64t*)&S->w3pk[((icp * 9 + k) * 32 + oc) * 2];
                    u64t D; PACK2(D, pe[ky * 5 + kx], po[ky * 5 + kx]);
                    FMA2(acc, D, W, acc);
                }
        }
        float lo, hi;
        UNPACK2(lo, hi, acc);
        float v = fmaxf(lo + hi + S->b3[oc], 0.f);
        v += __shfl_xor_sync(0xffffffffu, v, 1);
        v += __shfl_xor_sync(0xffffffffu, v, 2);
        if (pos == 0) S->s3[im][oc] = 0.25f * v;
    }
    __syncthreads();

    // ---- Dense + softmax + guards: warp 0 ----
    if (tid < 32) {
        if (tid < 20) {
            const int im = tid / 10, j = tid - im * 10;
            float v = S->db[j];
            #pragma unroll
            for (int k = 0; k < 32; k++) v += S->s3[im][k] * S->dwT[k * 10 + j];
            S->logits[im][j] = v;
        }
        __syncwarp();
        if (tid < 20) {
            const int im = tid / 10, j = tid - im * 10;
            float m = S->logits[im][0];
            #pragma unroll
            for (int k = 1; k < 10; k++) m = fmaxf(m, S->logits[im][k]);
            float sum = 0.f;
            #pragma unroll
            for (int k = 0; k < 10; k++) sum += __expf(S->logits[im][k] - m);
            const float p = __expf(S->logits[im][j] - m) / sum;
            S->p2[im][j] = p;
            out[(blockIdx.x * 2 + im) * 10 + j] = p;
        }
        __syncwarp();
        if (tid < 12) {
            const int im = tid / 6, j = tid - im * 6;
            const float* p = S->p2[im];
            float g;
            switch (j) {
                case 0:  g = p[8];         break;
                case 1:  g = p[4] + p[6];  break;
                case 2:  g = p[0] + p[2];  break;
                case 3:  g = p[7] + p[9];  break;
                case 4:  g = p[5];         break;
                default: g = p[1] + p[3];  break;
            }
            out[GUARD_BASE + (blockIdx.x * 2 + im) * 6 + j] = g;
        }
    }
}

// ---------------------------------------------------------------------------
// SFA: 32 blocks x 8 warps; warp w handles batch element b = blk*8 + w.
// Warp-private guard slice, M column in registers, state via shfl.
// ---------------------------------------------------------------------------
__global__ __launch_bounds__(256) void sfa_kernel(float* __restrict__ out)
{
    __shared__ float s_g[8][NSTEP * 6];

    const int tid  = threadIdx.x;
    const int w    = tid >> 5;
    const int lane = tid & 31;
    const int b    = blockIdx.x * 8 + w;

    const float* gbase = out + GUARD_BASE;
    #pragma unroll
    for (int k = lane; k < NSTEP * 6; k += 32) {
        const int n = k / 6, j = k - n * 6;
        s_g[w][k] = gbase[(n * BATCH + b) * 6 + j];
    }

    const int jj = (lane < 10) ? lane : 0;
    float Mr[6][10];
    #pragma unroll
    for (int r = 0; r < 6; r++)
        #pragma unroll
        for (int i = 0; i < 10; i++)
            Mr[r][i] = g_M[r * 100 + i * 10 + jj];
    __syncwarp();

    float st = (lane == 0) ? 1.f : 0.f;
    for (int n = 0; n < NSTEP; n++) {
        const float g0 = s_g[w][n * 6 + 0], g1 = s_g[w][n * 6 + 1], g2 = s_g[w][n * 6 + 2];
        const float g3 = s_g[w][n * 6 + 3], g4 = s_g[w][n * 6 + 4], g5 = s_g[w][n * 6 + 5];
        float a = 0.f;
        #pragma unroll
        for (int i = 0; i < 10; i++) {
            const float si = __shfl_sync(0xffffffff, st, i);
            const float mij = g0 * Mr[0][i] + g1 * Mr[1][i] + g2 * Mr[2][i]
                            + g3 * Mr[3][i] + g4 * Mr[4][i] + g5 * Mr[5][i];
            a += si * mij;
        }
        st = a;
    }
    if (lane < 10) out[STATE_BASE + b * 10 + lane] = st;
}

// ---------------------------------------------------------------------------
extern "C" void kernel_launch(void* const* d_in, const int* in_sizes, int n_in,
                              void* d_out, int out_size)
{
    const float* seq   = (const float*)d_in[0];
    const float* c1w   = (const float*)d_in[1];
    const float* c1b   = (const float*)d_in[2];
    const float* c2w   = (const float*)d_in[3];
    const float* c2b   = (const float*)d_in[4];
    const float* c3w   = (const float*)d_in[5];
    const float* c3b   = (const float*)d_in[6];
    const float* dw    = (const float*)d_in[7];
    const float* db    = (const float*)d_in[8];
    const float* trans = (const float*)d_in[9];
    float* out = (float*)d_out;

    const int smem_bytes = (int)sizeof(SmemLayout);
    cudaFuncSetAttribute(cnn_kernel, cudaFuncAttributeMaxDynamicSharedMemorySize,
                         smem_bytes);

    cnn_kernel<<<NIMG / 2, 256, smem_bytes>>>(seq, c1w, c1b, c2w, c2b,
                                              c3w, c3b, dw, db, trans, out);
    sfa_kernel<<<BATCH / 8, 256>>>(out);
}